// round 15
// baseline (speedup 1.0000x reference)
#include <cuda_runtime.h>
#include <cuda_fp16.h>
#include <cstdint>

// Problem constants (fixed shapes)
#define T_TOK 4096
#define HDIM  1024
#define FDIM  4096
#define EDIM  8
#define BM 128
#define BN 128
#define BKH 64          // gemm1 K halves per slab (4 x k16 steps)
#define ROWB 144        // gemm1 smem row stride bytes (128 data + 16 pad)
#define BKH2 128        // gemm2 K halves per slab (8 x k16 steps)
#define ROWB2 272       // gemm2 smem row stride bytes (256 data + 16 pad)
#define PADROWS 9216    // 8192 + 8*128 worst-case segment padding
#define NS1 (HDIM / BKH)        // 16
#define NS2H (FDIM / 2 / BKH2)  // 16 slabs per gemm2 K-half

// ---------------- scratch (static device globals; no allocation) ----------
__device__ __align__(16) __half g_wgup[(size_t)EDIM * 2 * FDIM * HDIM];
__device__ __align__(16) __half g_wdw[(size_t)EDIM * HDIM * FDIM];
__device__ __align__(16) __half g_x16[(size_t)T_TOK * HDIM];
__device__ __align__(16) __half g_h[(size_t)PADROWS * FDIM];
__device__ __align__(16) float  g_y[(size_t)PADROWS * HDIM];
__device__ int   g_perm_token[PADROWS];
__device__ float g_perm_weight[PADROWS];
__device__ int   g_te[T_TOK * 2];
__device__ float g_tw[T_TOK * 2];
__device__ int   g_counts[EDIM];
__device__ int   g_cursor[EDIM];
__device__ int   g_off[EDIM + 1];

// ---------------- helpers ---------------------------------------------------
__device__ __forceinline__ uint32_t h2u(__half2 h) { return *(uint32_t*)&h; }

__device__ __forceinline__ uint32_t smem_u32(const void* p) {
    uint32_t a;
    asm("{ .reg .u64 t; cvta.to.shared.u64 t, %1; cvt.u32.u64 %0, t; }"
        : "=r"(a) : "l"(p));
    return a;
}

__device__ __forceinline__ void ldsm4(uint32_t& r0, uint32_t& r1,
                                      uint32_t& r2, uint32_t& r3, uint32_t addr) {
    asm volatile("ldmatrix.sync.aligned.m8n8.x4.shared.b16 {%0,%1,%2,%3}, [%4];"
                 : "=r"(r0), "=r"(r1), "=r"(r2), "=r"(r3) : "r"(addr));
}

__device__ __forceinline__ void mma_f16(float c[4], const uint32_t a[4],
                                        uint32_t b0, uint32_t b1) {
    asm volatile(
        "mma.sync.aligned.m16n8k16.row.col.f32.f16.f16.f32 "
        "{%0,%1,%2,%3}, {%4,%5,%6,%7}, {%8,%9}, {%0,%1,%2,%3};\n"
        : "+f"(c[0]), "+f"(c[1]), "+f"(c[2]), "+f"(c[3])
        : "r"(a[0]), "r"(a[1]), "r"(a[2]), "r"(a[3]), "r"(b0), "r"(b1));
}

// ---------------- fp32 -> fp16 conversion (flat) -------------------------------
__global__ void cvt_kernel(const float* __restrict__ s, __half* __restrict__ d,
                           int n8) {
    int i = blockIdx.x * blockDim.x + threadIdx.x;
    if (i >= n8) return;
    const float4* s4 = (const float4*)s + (size_t)i * 2;
    float4 v0 = s4[0], v1 = s4[1];
    uint4 o;
    o.x = h2u(__floats2half2_rn(v0.x, v0.y));
    o.y = h2u(__floats2half2_rn(v0.z, v0.w));
    o.z = h2u(__floats2half2_rn(v1.x, v1.y));
    o.w = h2u(__floats2half2_rn(v1.z, v1.w));
    ((uint4*)d)[i] = o;
}

// ---------------- cvt for one column-half of gate_up ---------------------------
__global__ void cvt_gup_half_kernel(const float* __restrict__ s,
                                    __half* __restrict__ d, int half) {
    int i = blockIdx.x * blockDim.x + threadIdx.x;
    if (i >= EDIM * 4096 * 128) return;
    int rowIdx = i >> 7;
    int chunk = i & 127;
    int e = rowIdx >> 12;
    int rr = rowIdx & 4095;
    int isUp = rr >> 11;
    int r = rr & 2047;
    size_t srcRow = (size_t)e * 8192 + (size_t)isUp * 4096 +
                    (size_t)half * 2048 + (size_t)r;
    size_t off8 = srcRow * 128 + chunk;
    const float4* s4 = (const float4*)s + off8 * 2;
    float4 v0 = s4[0], v1 = s4[1];
    uint4 o;
    o.x = h2u(__floats2half2_rn(v0.x, v0.y));
    o.y = h2u(__floats2half2_rn(v0.z, v0.w));
    o.z = h2u(__floats2half2_rn(v1.x, v1.y));
    o.w = h2u(__floats2half2_rn(v1.z, v1.w));
    ((uint4*)d)[off8] = o;
}

// ---------------- init + zero output ------------------------------------------
__global__ void init_kernel() {
    int i = blockIdx.x * blockDim.x + threadIdx.x;
    if (i < PADROWS) {
        g_perm_token[i] = -1;
        g_perm_weight[i] = 0.f;
    }
    if (i < EDIM) g_counts[i] = 0;
}

__global__ void zero_out_kernel(float* __restrict__ out) {
    int i = blockIdx.x * blockDim.x + threadIdx.x;
    if (i < T_TOK * HDIM / 4)
        ((float4*)out)[i] = make_float4(0.f, 0.f, 0.f, 0.f);
}

// ---------------- router: logits + softmax top2 -----------------------------
__global__ void __launch_bounds__(128) router_kernel(
    const float* __restrict__ x, const float* __restrict__ gw,
    float* __restrict__ logits_out) {
    __shared__ float sgw[EDIM * HDIM];
    int tid = threadIdx.x;
    for (int i = tid; i < EDIM * HDIM; i += 128) sgw[i] = gw[i];
    __syncthreads();

    int warp = tid >> 5, lane = tid & 31;
    int t = blockIdx.x * 4 + warp;
    const float* xr = x + (size_t)t * HDIM;

    float acc[EDIM];
#pragma unroll
    for (int e = 0; e < EDIM; e++) acc[e] = 0.f;
    for (int j = lane; j < HDIM; j += 32) {
        float xv = xr[j];
#pragma unroll
        for (int e = 0; e < EDIM; e++) acc[e] = fmaf(xv, sgw[e * HDIM + j], acc[e]);
    }
#pragma unroll
    for (int e = 0; e < EDIM; e++)
#pragma unroll
        for (int o = 16; o > 0; o >>= 1)
            acc[e] += __shfl_xor_sync(0xffffffffu, acc[e], o);

    if (lane == 0) {
#pragma unroll
        for (int e = 0; e < EDIM; e++) logits_out[t * EDIM + e] = acc[e];
        int e0 = 0; float l0 = acc[0];
#pragma unroll
        for (int e = 1; e < EDIM; e++) if (acc[e] > l0) { l0 = acc[e]; e0 = e; }
        int e1 = -1; float l1 = -3.4e38f;
#pragma unroll
        for (int e = 0; e < EDIM; e++)
            if (e != e0 && acc[e] > l1) { l1 = acc[e]; e1 = e; }
        float r = expf(l1 - l0);
        float w0 = 1.f / (1.f + r);
        float w1 = r / (1.f + r);
        g_te[t * 2 + 0] = e0; g_tw[t * 2 + 0] = w0;
        g_te[t * 2 + 1] = e1; g_tw[t * 2 + 1] = w1;
        atomicAdd(&g_counts[e0], 1);
        atomicAdd(&g_counts[e1], 1);
    }
}

// ---------------- scan ------------------------------------------------------
__global__ void scan_kernel() {
    int off = 0;
    for (int e = 0; e < EDIM; e++) {
        g_off[e] = off;
        g_cursor[e] = off;
        off += ((g_counts[e] + BM - 1) / BM) * BM;
    }
    g_off[EDIM] = off;
}

// ---------------- scatter ---------------------------------------------------
__global__ void scatter_kernel() {
    int t = blockIdx.x * blockDim.x + threadIdx.x;
    if (t >= T_TOK) return;
#pragma unroll
    for (int k = 0; k < 2; k++) {
        int e = g_te[t * 2 + k];
        int pos = atomicAdd(&g_cursor[e], 1);
        g_perm_token[pos] = t;
        g_perm_weight[pos] = g_tw[t * 2 + k];
    }
}

// ---------------- GEMM1: h = silu(x@w1^T) * (x@w3^T) * route_w ---------------
// R13-proven core: 128x128 tile, 8 warps (64x32 warp tile x2 gemms), BKH=64.
__global__ void __launch_bounds__(256, 1) gemm1_kernel(int n0base) {
    extern __shared__ char sm1[];
    const uint32_t ABUF = 128 * ROWB;
    const uint32_t GOFF = 128 * ROWB;
    const uint32_t BBUF = 2 * 128 * ROWB;
    char* Asm = sm1;
    char* Bsm = sm1 + 2 * ABUF;
    uint32_t asB = smem_u32(Asm);
    uint32_t bsB = smem_u32(Bsm);

    int m0 = blockIdx.x * BM;
    if (m0 >= g_off[EDIM]) return;
    int n0 = n0base + blockIdx.y * BN;
    int e = 0;
    while (m0 >= g_off[e + 1]) e++;

    int tid = threadIdx.x;
    int r = tid >> 1;
    int seg = tid & 1;

    int tok = g_perm_token[m0 + r];
    const __half* arow = (tok >= 0)
        ? g_x16 + (size_t)tok * HDIM + seg * 32 : nullptr;
    const __half* bgrow = g_wgup + ((size_t)e * 2 * FDIM + (n0 + r)) * HDIM + seg * 32;
    const __half* burow = bgrow + (size_t)FDIM * HDIM;
    uint32_t stoff = (uint32_t)(r * ROWB + seg * 64);

    int warp = tid >> 5, lane = tid & 31;
    int gid = lane >> 2, tig = lane & 3;
    int wm = (warp & 1) * 64;
    int wn = (warp >> 1) * 32;

    uint32_t aLrow = (uint32_t)(wm + (lane & 15));
    uint32_t aLcol = (uint32_t)((lane >> 4) * 16);
    uint32_t bLrow = (uint32_t)(wn + (lane & 7) + ((lane >> 4) & 1) * 8);
    uint32_t bLcol = (uint32_t)(((lane >> 3) & 1) * 16);

    float acc[2][4][4][4];
#pragma unroll
    for (int g = 0; g < 2; g++)
#pragma unroll
        for (int mt = 0; mt < 4; mt++)
#pragma unroll
            for (int nt = 0; nt < 4; nt++)
#pragma unroll
                for (int i = 0; i < 4; i++) acc[g][mt][nt][i] = 0.f;

    const uint4 z4 = make_uint4(0, 0, 0, 0);
    uint4 pA[4], pG[4], pU[4];
#pragma unroll
    for (int i = 0; i < 4; i++) {
        pA[i] = arow ? *(const uint4*)(arow + i * 8) : z4;
        pG[i] = *(const uint4*)(bgrow + i * 8);
        pU[i] = *(const uint4*)(burow + i * 8);
    }

    for (int s = 0; s < NS1; s++) {
        int buf = s & 1;
        char* At = Asm + buf * ABUF;
        char* Bt = Bsm + buf * BBUF;
#pragma unroll
        for (int i = 0; i < 4; i++) {
            *(uint4*)(At + stoff + i * 16) = pA[i];
            *(uint4*)(Bt + stoff + i * 16) = pG[i];
            *(uint4*)(Bt + GOFF + stoff + i * 16) = pU[i];
        }
        __syncthreads();

        if (s + 1 < NS1) {
            int k = (s + 1) * BKH;
#pragma unroll
            for (int i = 0; i < 4; i++) {
                pA[i] = arow ? *(const uint4*)(arow + k + i * 8) : z4;
                pG[i] = *(const uint4*)(bgrow + k + i * 8);
                pU[i] = *(const uint4*)(burow + k + i * 8);
            }
        }

        uint32_t aTile = asB + buf * ABUF;
        uint32_t bTile = bsB + buf * BBUF;
#pragma unroll
        for (int ks = 0; ks < 4; ks++) {
            uint32_t kbA = ks * 32 + aLcol;
            uint32_t kbB = ks * 32 + bLcol;
            uint32_t a[4][4];
#pragma unroll
            for (int mt = 0; mt < 4; mt++)
                ldsm4(a[mt][0], a[mt][1], a[mt][2], a[mt][3],
                      aTile + (aLrow + mt * 16) * ROWB + kbA);
#pragma unroll
            for (int g = 0; g < 2; g++) {
#pragma unroll
                for (int np = 0; np < 2; np++) {
                    uint32_t b0, b1, b2, b3;
                    ldsm4(b0, b1, b2, b3,
                          bTile + g * GOFF + (bLrow + np * 16) * ROWB + kbB);
#pragma unroll
                    for (int mt = 0; mt < 4; mt++) {
                        mma_f16(acc[g][mt][np * 2 + 0], a[mt], b0, b1);
                        mma_f16(acc[g][mt][np * 2 + 1], a[mt], b2, b3);
                    }
                }
            }
        }
    }

#pragma unroll
    for (int mt = 0; mt < 4; mt++) {
        int rbase = m0 + wm + mt * 16 + gid;
        float wA = g_perm_weight[rbase];
        float wB = g_perm_weight[rbase + 8];
#pragma unroll
        for (int nt = 0; nt < 4; nt++) {
            int cbase = n0 + wn + nt * 8 + 2 * tig;
            float h0 = (acc[0][mt][nt][0] / (1.f + expf(-acc[0][mt][nt][0]))) *
                       acc[1][mt][nt][0] * wA;
            float h1 = (acc[0][mt][nt][1] / (1.f + expf(-acc[0][mt][nt][1]))) *
                       acc[1][mt][nt][1] * wA;
            float h2 = (acc[0][mt][nt][2] / (1.f + expf(-acc[0][mt][nt][2]))) *
                       acc[1][mt][nt][2] * wB;
            float h3 = (acc[0][mt][nt][3] / (1.f + expf(-acc[0][mt][nt][3]))) *
                       acc[1][mt][nt][3] * wB;
            *(uint32_t*)&g_h[(size_t)rbase * FDIM + cbase] =
                h2u(__floats2half2_rn(h0, h1));
            *(uint32_t*)&g_h[(size_t)(rbase + 8) * FDIM + cbase] =
                h2u(__floats2half2_rn(h2, h3));
        }
    }
}

// ---------------- GEMM2 (K-split, BKH2=128): stageB=0 -> g_y partial;
//                  stageB=1 -> + g_y, atomicAdd out. ---------------------------
__global__ void __launch_bounds__(256, 1) gemm2_kernel(float* __restrict__ out,
                                                       int kbase, int stageB) {
    extern __shared__ char sm2[];
    const uint32_t ABUF = 128 * ROWB2;   // 34816
    const uint32_t BBUF = 128 * ROWB2;
    char* Asm = sm2;
    char* Bsm = sm2 + 2 * ABUF;
    uint32_t asB = smem_u32(Asm);
    uint32_t bsB = smem_u32(Bsm);

    int m0 = blockIdx.x * BM;
    if (m0 >= g_off[EDIM]) return;
    int n0 = blockIdx.y * BN;
    int e = 0;
    while (m0 >= g_off[e + 1]) e++;

    int tid = threadIdx.x;
    int r = tid >> 1;            // 128 rows, 2 threads/row
    int seg = tid & 1;           // 128-byte (64-half) segment

    const __half* arow = g_h + (size_t)(m0 + r) * FDIM + kbase + seg * 64;
    const __half* brow = g_wdw + ((size_t)e * HDIM + (n0 + r)) * FDIM + kbase + seg * 64;
    uint32_t stoff = (uint32_t)(r * ROWB2 + seg * 128);

    int warp = tid >> 5, lane = tid & 31;
    int gid = lane >> 2, tig = lane & 3;
    int wm = (warp & 1) * 64;
    int wn = (warp >> 1) * 32;

    uint32_t aLrow = (uint32_t)(wm + (lane & 15));
    uint32_t aLcol = (uint32_t)((lane >> 4) * 16);
    uint32_t bLrow = (uint32_t)(wn + (lane & 7) + ((lane >> 4) & 1) * 8);
    uint32_t bLcol = (uint32_t)(((lane >> 3) & 1) * 16);

    float acc[4][4][4];
#pragma unroll
    for (int mt = 0; mt < 4; mt++)
#pragma unroll
        for (int nt = 0; nt < 4; nt++)
#pragma unroll
            for (int i = 0; i < 4; i++) acc[mt][nt][i] = 0.f;

    uint4 pA[8], pB[8];
#pragma unroll
    for (int i = 0; i < 8; i++) {
        pA[i] = *(const uint4*)(arow + i * 8);
        pB[i] = *(const uint4*)(brow + i * 8);
    }

    for (int s = 0; s < NS2H; s++) {
        int buf = s & 1;
        char* At = Asm + buf * ABUF;
        char* Bt = Bsm + buf * BBUF;
#pragma unroll
        for (int i = 0; i < 8; i++) {
            *(uint4*)(At + stoff + i * 16) = pA[i];
            *(uint4*)(Bt + stoff + i * 16) = pB[i];
        }
        __syncthreads();     // single barrier per (double-wide) slab

        if (s + 1 < NS2H) {
            int k = (s + 1) * BKH2;
#pragma unroll
            for (int i = 0; i < 8; i++) {
                pA[i] = *(const uint4*)(arow + k + i * 8);
                pB[i] = *(const uint4*)(brow + k + i * 8);
            }
        }

        uint32_t aTile = asB + buf * ABUF;
        uint32_t bTile = bsB + buf * BBUF;
#pragma unroll
        for (int ks = 0; ks < 8; ks++) {
            uint32_t kbA = ks * 32 + aLcol;
            uint32_t kbB = ks * 32 + bLcol;
            uint32_t a[4][4];
#pragma unroll
            for (int mt = 0; mt < 4; mt++)
                ldsm4(a[mt][0], a[mt][1], a[mt][2], a[mt][3],
                      aTile + (aLrow + mt * 16) * ROWB2 + kbA);
#pragma unroll
            for (int np = 0; np < 2; np++) {
                uint32_t b0, b1, b2, b3;
                ldsm4(b0, b1, b2, b3,
                      bTile + (bLrow + np * 16) * ROWB2 + kbB);
#pragma unroll
                for (int mt = 0; mt < 4; mt++) {
                    mma_f16(acc[mt][np * 2 + 0], a[mt], b0, b1);
                    mma_f16(acc[mt][np * 2 + 1], a[mt], b2, b3);
                }
            }
        }
    }

    if (!stageB) {
        // stage A: write fp32 partials to g_y (row-unique -> deterministic)
#pragma unroll
        for (int mt = 0; mt < 4; mt++) {
            int rbase = m0 + wm + mt * 16 + gid;
#pragma unroll
            for (int nt = 0; nt < 4; nt++) {
                int cbase = n0 + wn + nt * 8 + 2 * tig;
                *(float2*)&g_y[(size_t)rbase * HDIM + cbase] =
                    make_float2(acc[mt][nt][0], acc[mt][nt][1]);
                *(float2*)&g_y[(size_t)(rbase + 8) * HDIM + cbase] =
                    make_float2(acc[mt][nt][2], acc[mt][nt][3]);
            }
        }
    } else {
        // stage B: total = partial + acc; atomicAdd into out (2 contributors
        // per element -> commutative -> deterministic)
#pragma unroll
        for (int mt = 0; mt < 4; mt++) {
            int rbase = m0 + wm + mt * 16 + gid;
            int tok0 = g_perm_token[rbase];
            int tok1 = g_perm_token[rbase + 8];
#pragma unroll
            for (int nt = 0; nt < 4; nt++) {
                int cbase = n0 + wn + nt * 8 + 2 * tig;
                float2 y0 = *(float2*)&g_y[(size_t)rbase * HDIM + cbase];
                float2 y1 = *(float2*)&g_y[(size_t)(rbase + 8) * HDIM + cbase];
                if (tok0 >= 0) {
                    atomicAdd(&out[(size_t)tok0 * HDIM + cbase],
                              acc[mt][nt][0] + y0.x);
                    atomicAdd(&out[(size_t)tok0 * HDIM + cbase + 1],
                              acc[mt][nt][1] + y0.y);
                }
                if (tok1 >= 0) {
                    atomicAdd(&out[(size_t)tok1 * HDIM + cbase],
                              acc[mt][nt][2] + y1.x);
                    atomicAdd(&out[(size_t)tok1 * HDIM + cbase + 1],
                              acc[mt][nt][3] + y1.y);
                }
            }
        }
    }
}

// ---------------- launcher ----------------------------------------------------
extern "C" void kernel_launch(void* const* d_in, const int* in_sizes, int n_in,
                              void* d_out, int out_size) {
    const float* x   = (const float*)d_in[0];   // (2,2048,1024)
    const float* gw  = (const float*)d_in[1];   // (8,1024)
    const float* gup = (const float*)d_in[2];   // (8,8192,1024)
    const float* dw  = (const float*)d_in[3];   // (8,1024,4096)
    float* out = (float*)d_out;                 // out (4194304) ++ logits (32768)
    float* logits = out + (size_t)T_TOK * HDIM;

    const int smem1 = 2 * 128 * ROWB + 2 * 2 * 128 * ROWB;  // 110592 B
    const int smem2 = 2 * 128 * ROWB2 + 2 * 128 * ROWB2;    // 139264 B
    cudaFuncSetAttribute(gemm1_kernel, cudaFuncAttributeMaxDynamicSharedMemorySize, smem1);
    cudaFuncSetAttribute(gemm2_kernel, cudaFuncAttributeMaxDynamicSharedMemorySize, smem2);

    __half* d_wgup; cudaGetSymbolAddress((void**)&d_wgup, g_wgup);
    __half* d_wdw;  cudaGetSymbolAddress((void**)&d_wdw,  g_wdw);
    __half* d_x16;  cudaGetSymbolAddress((void**)&d_x16,  g_x16);

    static cudaStream_t s2 = nullptr, s3 = nullptr, s4 = nullptr;
    static cudaEvent_t evFork = nullptr, evCvt0 = nullptr, evH1 = nullptr,
                       evDW = nullptr, evRoute = nullptr, evG1h0 = nullptr,
                       evA = nullptr;
    if (!s2) {
        cudaStreamCreateWithFlags(&s2, cudaStreamNonBlocking);
        cudaStreamCreateWithFlags(&s3, cudaStreamNonBlocking);
        cudaStreamCreateWithFlags(&s4, cudaStreamNonBlocking);
        cudaEventCreateWithFlags(&evFork, cudaEventDisableTiming);
        cudaEventCreateWithFlags(&evCvt0, cudaEventDisableTiming);
        cudaEventCreateWithFlags(&evH1, cudaEventDisableTiming);
        cudaEventCreateWithFlags(&evDW, cudaEventDisableTiming);
        cudaEventCreateWithFlags(&evRoute, cudaEventDisableTiming);
        cudaEventCreateWithFlags(&evG1h0, cudaEventDisableTiming);
        cudaEventCreateWithFlags(&evA, cudaEventDisableTiming);
    }

    cudaEventRecord(evFork, 0);
    cudaStreamWaitEvent(s3, evFork, 0);

    // s3: output zero + routing chain (hidden under cvts on main)
    zero_out_kernel<<<(T_TOK * HDIM / 4 + 255) / 256, 256, 0, s3>>>(out);
    init_kernel<<<(PADROWS + 255) / 256, 256, 0, s3>>>();
    router_kernel<<<T_TOK / 4, 128, 0, s3>>>(x, gw, logits);
    scan_kernel<<<1, 1, 0, s3>>>();
    scatter_kernel<<<(T_TOK + 255) / 256, 256, 0, s3>>>();
    cudaEventRecord(evRoute, s3);

    // main: x cvt + first gate_up half (minimal serial prefix)
    cvt_kernel<<<(T_TOK * HDIM / 8 + 255) / 256, 256>>>(x, d_x16,
        T_TOK * HDIM / 8);
    cvt_gup_half_kernel<<<(EDIM * 4096 * 128 + 255) / 256, 256>>>(gup, d_wgup, 0);
    cudaEventRecord(evCvt0, 0);

    // s2: second gate_up half + down weights (overlap gemm1 half 0)
    cudaStreamWaitEvent(s2, evCvt0, 0);
    cvt_gup_half_kernel<<<(EDIM * 4096 * 128 + 255) / 256, 256, 0, s2>>>(
        gup, d_wgup, 1);
    cudaEventRecord(evH1, s2);
    cvt_kernel<<<(EDIM * HDIM * FDIM / 8 + 255) / 256, 256, 0, s2>>>(
        dw, d_wdw, EDIM * HDIM * FDIM / 8);
    cudaEventRecord(evDW, s2);

    // main: gemm1 half 0 (produces g_h cols [0,2048))
    cudaStreamWaitEvent(0, evRoute, 0);
    gemm1_kernel<<<dim3(PADROWS / BM, 16), 256, smem1>>>(0);
    cudaEventRecord(evG1h0, 0);

    // s4: gemm2 stage A (K half 0) — overlaps gemm1 half 1, fills its tail
    cudaStreamWaitEvent(s4, evG1h0, 0);
    cudaStreamWaitEvent(s4, evDW, 0);
    gemm2_kernel<<<dim3(PADROWS / BM, HDIM / BN), 256, smem2, s4>>>(out, 0, 0);
    cudaEventRecord(evA, s4);

    // main: gemm1 half 1, then gemm2 stage B (needs g_h cols [2048,4096) + g_y)
    cudaStreamWaitEvent(0, evH1, 0);
    gemm1_kernel<<<dim3(PADROWS / BM, 16), 256, smem1>>>(2048);
    cudaStreamWaitEvent(0, evA, 0);
    gemm2_kernel<<<dim3(PADROWS / BM, HDIM / BN), 256, smem2>>>(out, FDIM / 2, 1);
    (void)in_sizes; (void)n_in; (void)out_size;
}

// round 16
// speedup vs baseline: 1.1137x; 1.1137x over previous
#include <cuda_runtime.h>
#include <cuda_fp16.h>
#include <cstdint>

// Problem constants (fixed shapes)
#define T_TOK 4096
#define HDIM  1024
#define FDIM  4096
#define EDIM  8
#define BM 128
#define BN 128
#define BKH 64          // K halves per slab (4 x k16 mma steps)
#define ROWB 144        // smem row stride bytes (128 data + 16 pad)
#define PADROWS 9216    // 8192 + 8*128 worst-case segment padding
#define NS1 (HDIM / BKH)       // 16
#define NS2H (FDIM / 2 / BKH)  // 32 slabs per gemm2 K-half

// ---------------- scratch (static device globals; no allocation) ----------
__device__ __align__(16) __half g_wgup[(size_t)EDIM * 2 * FDIM * HDIM];
__device__ __align__(16) __half g_wdw[(size_t)EDIM * HDIM * FDIM];
__device__ __align__(16) __half g_x16[(size_t)T_TOK * HDIM];
__device__ __align__(16) __half g_h[(size_t)PADROWS * FDIM];
__device__ __align__(16) float  g_y[(size_t)PADROWS * HDIM];
__device__ int   g_perm_token[PADROWS];
__device__ float g_perm_weight[PADROWS];
__device__ int   g_te[T_TOK * 2];
__device__ float g_tw[T_TOK * 2];
__device__ int   g_counts[EDIM];
__device__ int   g_cursor[EDIM];
__device__ int   g_off[EDIM + 1];

// ---------------- helpers ---------------------------------------------------
__device__ __forceinline__ uint32_t h2u(__half2 h) { return *(uint32_t*)&h; }

__device__ __forceinline__ uint32_t smem_u32(const void* p) {
    uint32_t a;
    asm("{ .reg .u64 t; cvta.to.shared.u64 t, %1; cvt.u32.u64 %0, t; }"
        : "=r"(a) : "l"(p));
    return a;
}

__device__ __forceinline__ void ldsm4(uint32_t& r0, uint32_t& r1,
                                      uint32_t& r2, uint32_t& r3, uint32_t addr) {
    asm volatile("ldmatrix.sync.aligned.m8n8.x4.shared.b16 {%0,%1,%2,%3}, [%4];"
                 : "=r"(r0), "=r"(r1), "=r"(r2), "=r"(r3) : "r"(addr));
}

__device__ __forceinline__ void mma_f16(float c[4], const uint32_t a[4],
                                        uint32_t b0, uint32_t b1) {
    asm volatile(
        "mma.sync.aligned.m16n8k16.row.col.f32.f16.f16.f32 "
        "{%0,%1,%2,%3}, {%4,%5,%6,%7}, {%8,%9}, {%0,%1,%2,%3};\n"
        : "+f"(c[0]), "+f"(c[1]), "+f"(c[2]), "+f"(c[3])
        : "r"(a[0]), "r"(a[1]), "r"(a[2]), "r"(a[3]), "r"(b0), "r"(b1));
}

// ---------------- fp32 -> fp16 conversion (flat) -------------------------------
__global__ void cvt_kernel(const float* __restrict__ s, __half* __restrict__ d,
                           int n8) {
    int i = blockIdx.x * blockDim.x + threadIdx.x;
    if (i >= n8) return;
    const float4* s4 = (const float4*)s + (size_t)i * 2;
    float4 v0 = s4[0], v1 = s4[1];
    uint4 o;
    o.x = h2u(__floats2half2_rn(v0.x, v0.y));
    o.y = h2u(__floats2half2_rn(v0.z, v0.w));
    o.z = h2u(__floats2half2_rn(v1.x, v1.y));
    o.w = h2u(__floats2half2_rn(v1.z, v1.w));
    ((uint4*)d)[i] = o;
}

// ---------------- cvt for one column-quarter of gate_up ------------------------
// quarter q covers h-cols [q*1024,(q+1)*1024): gate rows e*8192+q*1024+r and
// up rows e*8192+4096+q*1024+r, r in [0,1024).
__global__ void cvt_gup_quarter_kernel(const float* __restrict__ s,
                                       __half* __restrict__ d, int quarter) {
    int i = blockIdx.x * blockDim.x + threadIdx.x;   // over E*2048*128 chunks
    if (i >= EDIM * 2048 * 128) return;
    int rowIdx = i >> 7;
    int chunk = i & 127;
    int e = rowIdx >> 11;
    int rr = rowIdx & 2047;
    int isUp = rr >> 10;
    int r = rr & 1023;
    size_t srcRow = (size_t)e * 8192 + (size_t)isUp * 4096 +
                    (size_t)quarter * 1024 + (size_t)r;
    size_t off8 = srcRow * 128 + chunk;
    const float4* s4 = (const float4*)s + off8 * 2;
    float4 v0 = s4[0], v1 = s4[1];
    uint4 o;
    o.x = h2u(__floats2half2_rn(v0.x, v0.y));
    o.y = h2u(__floats2half2_rn(v0.z, v0.w));
    o.z = h2u(__floats2half2_rn(v1.x, v1.y));
    o.w = h2u(__floats2half2_rn(v1.z, v1.w));
    ((uint4*)d)[off8] = o;
}

// ---------------- init + zero output ------------------------------------------
__global__ void init_kernel() {
    int i = blockIdx.x * blockDim.x + threadIdx.x;
    if (i < PADROWS) {
        g_perm_token[i] = -1;
        g_perm_weight[i] = 0.f;
    }
    if (i < EDIM) g_counts[i] = 0;
}

__global__ void zero_out_kernel(float* __restrict__ out) {
    int i = blockIdx.x * blockDim.x + threadIdx.x;
    if (i < T_TOK * HDIM / 4)
        ((float4*)out)[i] = make_float4(0.f, 0.f, 0.f, 0.f);
}

// ---------------- router: logits + softmax top2 -----------------------------
__global__ void __launch_bounds__(128) router_kernel(
    const float* __restrict__ x, const float* __restrict__ gw,
    float* __restrict__ logits_out) {
    __shared__ float sgw[EDIM * HDIM];
    int tid = threadIdx.x;
    for (int i = tid; i < EDIM * HDIM; i += 128) sgw[i] = gw[i];
    __syncthreads();

    int warp = tid >> 5, lane = tid & 31;
    int t = blockIdx.x * 4 + warp;
    const float* xr = x + (size_t)t * HDIM;

    float acc[EDIM];
#pragma unroll
    for (int e = 0; e < EDIM; e++) acc[e] = 0.f;
    for (int j = lane; j < HDIM; j += 32) {
        float xv = xr[j];
#pragma unroll
        for (int e = 0; e < EDIM; e++) acc[e] = fmaf(xv, sgw[e * HDIM + j], acc[e]);
    }
#pragma unroll
    for (int e = 0; e < EDIM; e++)
#pragma unroll
        for (int o = 16; o > 0; o >>= 1)
            acc[e] += __shfl_xor_sync(0xffffffffu, acc[e], o);

    if (lane == 0) {
#pragma unroll
        for (int e = 0; e < EDIM; e++) logits_out[t * EDIM + e] = acc[e];
        int e0 = 0; float l0 = acc[0];
#pragma unroll
        for (int e = 1; e < EDIM; e++) if (acc[e] > l0) { l0 = acc[e]; e0 = e; }
        int e1 = -1; float l1 = -3.4e38f;
#pragma unroll
        for (int e = 0; e < EDIM; e++)
            if (e != e0 && acc[e] > l1) { l1 = acc[e]; e1 = e; }
        float r = expf(l1 - l0);
        float w0 = 1.f / (1.f + r);
        float w1 = r / (1.f + r);
        g_te[t * 2 + 0] = e0; g_tw[t * 2 + 0] = w0;
        g_te[t * 2 + 1] = e1; g_tw[t * 2 + 1] = w1;
        atomicAdd(&g_counts[e0], 1);
        atomicAdd(&g_counts[e1], 1);
    }
}

// ---------------- scan ------------------------------------------------------
__global__ void scan_kernel() {
    int off = 0;
    for (int e = 0; e < EDIM; e++) {
        g_off[e] = off;
        g_cursor[e] = off;
        off += ((g_counts[e] + BM - 1) / BM) * BM;
    }
    g_off[EDIM] = off;
}

// ---------------- scatter ---------------------------------------------------
__global__ void scatter_kernel() {
    int t = blockIdx.x * blockDim.x + threadIdx.x;
    if (t >= T_TOK) return;
#pragma unroll
    for (int k = 0; k < 2; k++) {
        int e = g_te[t * 2 + k];
        int pos = atomicAdd(&g_cursor[e], 1);
        g_perm_token[pos] = t;
        g_perm_weight[pos] = g_tw[t * 2 + k];
    }
}

// ---------------- GEMM1: h = silu(x@w1^T) * (x@w3^T) * route_w ---------------
// R13 core, byte-identical.
__global__ void __launch_bounds__(256, 1) gemm1_kernel(int n0base) {
    extern __shared__ char sm1[];
    const uint32_t ABUF = 128 * ROWB;
    const uint32_t GOFF = 128 * ROWB;
    const uint32_t BBUF = 2 * 128 * ROWB;
    char* Asm = sm1;
    char* Bsm = sm1 + 2 * ABUF;
    uint32_t asB = smem_u32(Asm);
    uint32_t bsB = smem_u32(Bsm);

    int m0 = blockIdx.x * BM;
    if (m0 >= g_off[EDIM]) return;
    int n0 = n0base + blockIdx.y * BN;
    int e = 0;
    while (m0 >= g_off[e + 1]) e++;

    int tid = threadIdx.x;
    int r = tid >> 1;
    int seg = tid & 1;

    int tok = g_perm_token[m0 + r];
    const __half* arow = (tok >= 0)
        ? g_x16 + (size_t)tok * HDIM + seg * 32 : nullptr;
    const __half* bgrow = g_wgup + ((size_t)e * 2 * FDIM + (n0 + r)) * HDIM + seg * 32;
    const __half* burow = bgrow + (size_t)FDIM * HDIM;
    uint32_t stoff = (uint32_t)(r * ROWB + seg * 64);

    int warp = tid >> 5, lane = tid & 31;
    int gid = lane >> 2, tig = lane & 3;
    int wm = (warp & 1) * 64;
    int wn = (warp >> 1) * 32;

    uint32_t aLrow = (uint32_t)(wm + (lane & 15));
    uint32_t aLcol = (uint32_t)((lane >> 4) * 16);
    uint32_t bLrow = (uint32_t)(wn + (lane & 7) + ((lane >> 4) & 1) * 8);
    uint32_t bLcol = (uint32_t)(((lane >> 3) & 1) * 16);

    float acc[2][4][4][4];
#pragma unroll
    for (int g = 0; g < 2; g++)
#pragma unroll
        for (int mt = 0; mt < 4; mt++)
#pragma unroll
            for (int nt = 0; nt < 4; nt++)
#pragma unroll
                for (int i = 0; i < 4; i++) acc[g][mt][nt][i] = 0.f;

    const uint4 z4 = make_uint4(0, 0, 0, 0);
    uint4 pA[4], pG[4], pU[4];
#pragma unroll
    for (int i = 0; i < 4; i++) {
        pA[i] = arow ? *(const uint4*)(arow + i * 8) : z4;
        pG[i] = *(const uint4*)(bgrow + i * 8);
        pU[i] = *(const uint4*)(burow + i * 8);
    }

    for (int s = 0; s < NS1; s++) {
        int buf = s & 1;
        char* At = Asm + buf * ABUF;
        char* Bt = Bsm + buf * BBUF;
#pragma unroll
        for (int i = 0; i < 4; i++) {
            *(uint4*)(At + stoff + i * 16) = pA[i];
            *(uint4*)(Bt + stoff + i * 16) = pG[i];
            *(uint4*)(Bt + GOFF + stoff + i * 16) = pU[i];
        }
        __syncthreads();

        if (s + 1 < NS1) {
            int k = (s + 1) * BKH;
#pragma unroll
            for (int i = 0; i < 4; i++) {
                pA[i] = arow ? *(const uint4*)(arow + k + i * 8) : z4;
                pG[i] = *(const uint4*)(bgrow + k + i * 8);
                pU[i] = *(const uint4*)(burow + k + i * 8);
            }
        }

        uint32_t aTile = asB + buf * ABUF;
        uint32_t bTile = bsB + buf * BBUF;
#pragma unroll
        for (int ks = 0; ks < 4; ks++) {
            uint32_t kbA = ks * 32 + aLcol;
            uint32_t kbB = ks * 32 + bLcol;
            uint32_t a[4][4];
#pragma unroll
            for (int mt = 0; mt < 4; mt++)
                ldsm4(a[mt][0], a[mt][1], a[mt][2], a[mt][3],
                      aTile + (aLrow + mt * 16) * ROWB + kbA);
#pragma unroll
            for (int g = 0; g < 2; g++) {
#pragma unroll
                for (int np = 0; np < 2; np++) {
                    uint32_t b0, b1, b2, b3;
                    ldsm4(b0, b1, b2, b3,
                          bTile + g * GOFF + (bLrow + np * 16) * ROWB + kbB);
#pragma unroll
                    for (int mt = 0; mt < 4; mt++) {
                        mma_f16(acc[g][mt][np * 2 + 0], a[mt], b0, b1);
                        mma_f16(acc[g][mt][np * 2 + 1], a[mt], b2, b3);
                    }
                }
            }
        }
    }

#pragma unroll
    for (int mt = 0; mt < 4; mt++) {
        int rbase = m0 + wm + mt * 16 + gid;
        float wA = g_perm_weight[rbase];
        float wB = g_perm_weight[rbase + 8];
#pragma unroll
        for (int nt = 0; nt < 4; nt++) {
            int cbase = n0 + wn + nt * 8 + 2 * tig;
            float h0 = (acc[0][mt][nt][0] / (1.f + expf(-acc[0][mt][nt][0]))) *
                       acc[1][mt][nt][0] * wA;
            float h1 = (acc[0][mt][nt][1] / (1.f + expf(-acc[0][mt][nt][1]))) *
                       acc[1][mt][nt][1] * wA;
            float h2 = (acc[0][mt][nt][2] / (1.f + expf(-acc[0][mt][nt][2]))) *
                       acc[1][mt][nt][2] * wB;
            float h3 = (acc[0][mt][nt][3] / (1.f + expf(-acc[0][mt][nt][3]))) *
                       acc[1][mt][nt][3] * wB;
            *(uint32_t*)&g_h[(size_t)rbase * FDIM + cbase] =
                h2u(__floats2half2_rn(h0, h1));
            *(uint32_t*)&g_h[(size_t)(rbase + 8) * FDIM + cbase] =
                h2u(__floats2half2_rn(h2, h3));
        }
    }
}

// ---------------- GEMM2 (K-split): R13 core, byte-identical --------------------
__global__ void __launch_bounds__(256, 1) gemm2_kernel(float* __restrict__ out,
                                                       int kbase, int stageB) {
    extern __shared__ char sm2[];
    const uint32_t ABUF = 128 * ROWB;
    const uint32_t BBUF = 128 * ROWB;
    char* Asm = sm2;
    char* Bsm = sm2 + 2 * ABUF;
    uint32_t asB = smem_u32(Asm);
    uint32_t bsB = smem_u32(Bsm);

    int m0 = blockIdx.x * BM;
    if (m0 >= g_off[EDIM]) return;
    int n0 = blockIdx.y * BN;
    int e = 0;
    while (m0 >= g_off[e + 1]) e++;

    int tid = threadIdx.x;
    int r = tid >> 1;
    int seg = tid & 1;

    const __half* arow = g_h + (size_t)(m0 + r) * FDIM + kbase + seg * 32;
    const __half* brow = g_wdw + ((size_t)e * HDIM + (n0 + r)) * FDIM + kbase + seg * 32;
    uint32_t stoff = (uint32_t)(r * ROWB + seg * 64);

    int warp = tid >> 5, lane = tid & 31;
    int gid = lane >> 2, tig = lane & 3;
    int wm = (warp & 1) * 64;
    int wn = (warp >> 1) * 32;

    uint32_t aLrow = (uint32_t)(wm + (lane & 15));
    uint32_t aLcol = (uint32_t)((lane >> 4) * 16);
    uint32_t bLrow = (uint32_t)(wn + (lane & 7) + ((lane >> 4) & 1) * 8);
    uint32_t bLcol = (uint32_t)(((lane >> 3) & 1) * 16);

    float acc[4][4][4];
#pragma unroll
    for (int mt = 0; mt < 4; mt++)
#pragma unroll
        for (int nt = 0; nt < 4; nt++)
#pragma unroll
            for (int i = 0; i < 4; i++) acc[mt][nt][i] = 0.f;

    uint4 pA[4], pB[4];
#pragma unroll
    for (int i = 0; i < 4; i++) {
        pA[i] = *(const uint4*)(arow + i * 8);
        pB[i] = *(const uint4*)(brow + i * 8);
    }

    for (int s = 0; s < NS2H; s++) {
        int buf = s & 1;
        char* At = Asm + buf * ABUF;
        char* Bt = Bsm + buf * BBUF;
#pragma unroll
        for (int i = 0; i < 4; i++) {
            *(uint4*)(At + stoff + i * 16) = pA[i];
            *(uint4*)(Bt + stoff + i * 16) = pB[i];
        }
        __syncthreads();

        if (s + 1 < NS2H) {
            int k = (s + 1) * BKH;
#pragma unroll
            for (int i = 0; i < 4; i++) {
                pA[i] = *(const uint4*)(arow + k + i * 8);
                pB[i] = *(const uint4*)(brow + k + i * 8);
            }
        }

        uint32_t aTile = asB + buf * ABUF;
        uint32_t bTile = bsB + buf * BBUF;
#pragma unroll
        for (int ks = 0; ks < 4; ks++) {
            uint32_t kbA = ks * 32 + aLcol;
            uint32_t kbB = ks * 32 + bLcol;
            uint32_t a[4][4];
#pragma unroll
            for (int mt = 0; mt < 4; mt++)
                ldsm4(a[mt][0], a[mt][1], a[mt][2], a[mt][3],
                      aTile + (aLrow + mt * 16) * ROWB + kbA);
#pragma unroll
            for (int np = 0; np < 2; np++) {
                uint32_t b0, b1, b2, b3;
                ldsm4(b0, b1, b2, b3,
                      bTile + (bLrow + np * 16) * ROWB + kbB);
#pragma unroll
                for (int mt = 0; mt < 4; mt++) {
                    mma_f16(acc[mt][np * 2 + 0], a[mt], b0, b1);
                    mma_f16(acc[mt][np * 2 + 1], a[mt], b2, b3);
                }
            }
        }
    }

    if (!stageB) {
#pragma unroll
        for (int mt = 0; mt < 4; mt++) {
            int rbase = m0 + wm + mt * 16 + gid;
#pragma unroll
            for (int nt = 0; nt < 4; nt++) {
                int cbase = n0 + wn + nt * 8 + 2 * tig;
                *(float2*)&g_y[(size_t)rbase * HDIM + cbase] =
                    make_float2(acc[mt][nt][0], acc[mt][nt][1]);
                *(float2*)&g_y[(size_t)(rbase + 8) * HDIM + cbase] =
                    make_float2(acc[mt][nt][2], acc[mt][nt][3]);
            }
        }
    } else {
#pragma unroll
        for (int mt = 0; mt < 4; mt++) {
            int rbase = m0 + wm + mt * 16 + gid;
            int tok0 = g_perm_token[rbase];
            int tok1 = g_perm_token[rbase + 8];
#pragma unroll
            for (int nt = 0; nt < 4; nt++) {
                int cbase = n0 + wn + nt * 8 + 2 * tig;
                float2 y0 = *(float2*)&g_y[(size_t)rbase * HDIM + cbase];
                float2 y1 = *(float2*)&g_y[(size_t)(rbase + 8) * HDIM + cbase];
                if (tok0 >= 0) {
                    atomicAdd(&out[(size_t)tok0 * HDIM + cbase],
                              acc[mt][nt][0] + y0.x);
                    atomicAdd(&out[(size_t)tok0 * HDIM + cbase + 1],
                              acc[mt][nt][1] + y0.y);
                }
                if (tok1 >= 0) {
                    atomicAdd(&out[(size_t)tok1 * HDIM + cbase],
                              acc[mt][nt][2] + y1.x);
                    atomicAdd(&out[(size_t)tok1 * HDIM + cbase + 1],
                              acc[mt][nt][3] + y1.y);
                }
            }
        }
    }
}

// ---------------- launcher ----------------------------------------------------
extern "C" void kernel_launch(void* const* d_in, const int* in_sizes, int n_in,
                              void* d_out, int out_size) {
    const float* x   = (const float*)d_in[0];   // (2,2048,1024)
    const float* gw  = (const float*)d_in[1];   // (8,1024)
    const float* gup = (const float*)d_in[2];   // (8,8192,1024)
    const float* dw  = (const float*)d_in[3];   // (8,1024,4096)
    float* out = (float*)d_out;                 // out (4194304) ++ logits (32768)
    float* logits = out + (size_t)T_TOK * HDIM;

    const int smem1 = 2 * 128 * ROWB + 2 * 2 * 128 * ROWB;  // 110592 B
    const int smem2 = 2 * 128 * ROWB + 2 * 128 * ROWB;      //  73728 B
    cudaFuncSetAttribute(gemm1_kernel, cudaFuncAttributeMaxDynamicSharedMemorySize, smem1);
    cudaFuncSetAttribute(gemm2_kernel, cudaFuncAttributeMaxDynamicSharedMemorySize, smem2);

    __half* d_wgup; cudaGetSymbolAddress((void**)&d_wgup, g_wgup);
    __half* d_wdw;  cudaGetSymbolAddress((void**)&d_wdw,  g_wdw);
    __half* d_x16;  cudaGetSymbolAddress((void**)&d_x16,  g_x16);

    static cudaStream_t s2 = nullptr, s3 = nullptr, s4 = nullptr;
    static cudaEvent_t evFork = nullptr, evQ0 = nullptr, evQ1 = nullptr,
                       evQ2 = nullptr, evQ3 = nullptr, evDW = nullptr,
                       evRoute = nullptr, evG1q1 = nullptr, evA = nullptr;
    if (!s2) {
        cudaStreamCreateWithFlags(&s2, cudaStreamNonBlocking);
        cudaStreamCreateWithFlags(&s3, cudaStreamNonBlocking);
        cudaStreamCreateWithFlags(&s4, cudaStreamNonBlocking);
        cudaEventCreateWithFlags(&evFork, cudaEventDisableTiming);
        cudaEventCreateWithFlags(&evQ0, cudaEventDisableTiming);
        cudaEventCreateWithFlags(&evQ1, cudaEventDisableTiming);
        cudaEventCreateWithFlags(&evQ2, cudaEventDisableTiming);
        cudaEventCreateWithFlags(&evQ3, cudaEventDisableTiming);
        cudaEventCreateWithFlags(&evDW, cudaEventDisableTiming);
        cudaEventCreateWithFlags(&evRoute, cudaEventDisableTiming);
        cudaEventCreateWithFlags(&evG1q1, cudaEventDisableTiming);
        cudaEventCreateWithFlags(&evA, cudaEventDisableTiming);
    }

    const int QCHUNK = EDIM * 2048 * 128;   // threads per quarter cvt

    cudaEventRecord(evFork, 0);
    cudaStreamWaitEvent(s3, evFork, 0);

    // s3: output zero + routing chain (hidden under cvts on main)
    zero_out_kernel<<<(T_TOK * HDIM / 4 + 255) / 256, 256, 0, s3>>>(out);
    init_kernel<<<(PADROWS + 255) / 256, 256, 0, s3>>>();
    router_kernel<<<T_TOK / 4, 128, 0, s3>>>(x, gw, logits);
    scan_kernel<<<1, 1, 0, s3>>>();
    scatter_kernel<<<(T_TOK + 255) / 256, 256, 0, s3>>>();
    cudaEventRecord(evRoute, s3);

    // main: x cvt + first gate_up quarter (minimal serial prefix)
    cvt_kernel<<<(T_TOK * HDIM / 8 + 255) / 256, 256>>>(x, d_x16,
        T_TOK * HDIM / 8);
    cvt_gup_quarter_kernel<<<(QCHUNK + 255) / 256, 256>>>(gup, d_wgup, 0);
    cudaEventRecord(evQ0, 0);

    // s2: remaining quarters + down weights (overlap gemm1 quarters on main)
    cudaStreamWaitEvent(s2, evQ0, 0);
    cvt_gup_quarter_kernel<<<(QCHUNK + 255) / 256, 256, 0, s2>>>(gup, d_wgup, 1);
    cudaEventRecord(evQ1, s2);
    cvt_gup_quarter_kernel<<<(QCHUNK + 255) / 256, 256, 0, s2>>>(gup, d_wgup, 2);
    cudaEventRecord(evQ2, s2);
    cvt_gup_quarter_kernel<<<(QCHUNK + 255) / 256, 256, 0, s2>>>(gup, d_wgup, 3);
    cudaEventRecord(evQ3, s2);
    cvt_kernel<<<(EDIM * HDIM * FDIM / 8 + 255) / 256, 256, 0, s2>>>(
        dw, d_wdw, EDIM * HDIM * FDIM / 8);
    cudaEventRecord(evDW, s2);

    // main: gemm1 quarters (each 1024 h-cols; grid y = 8)
    cudaStreamWaitEvent(0, evRoute, 0);
    gemm1_kernel<<<dim3(PADROWS / BM, 8), 256, smem1>>>(0);
    cudaStreamWaitEvent(0, evQ1, 0);
    gemm1_kernel<<<dim3(PADROWS / BM, 8), 256, smem1>>>(1024);
    cudaEventRecord(evG1q1, 0);   // g_h cols [0,2048) complete

    // s4: gemm2 stage A (K half 0) — overlaps gemm1 q2/q3, fills tails
    cudaStreamWaitEvent(s4, evG1q1, 0);
    cudaStreamWaitEvent(s4, evDW, 0);
    gemm2_kernel<<<dim3(PADROWS / BM, HDIM / BN), 256, smem2, s4>>>(out, 0, 0);
    cudaEventRecord(evA, s4);

    // main: gemm1 q2, q3, then gemm2 stage B
    cudaStreamWaitEvent(0, evQ2, 0);
    gemm1_kernel<<<dim3(PADROWS / BM, 8), 256, smem1>>>(2048);
    cudaStreamWaitEvent(0, evQ3, 0);
    gemm1_kernel<<<dim3(PADROWS / BM, 8), 256, smem1>>>(3072);
    cudaStreamWaitEvent(0, evA, 0);
    gemm2_kernel<<<dim3(PADROWS / BM, HDIM / BN), 256, smem2>>>(out, FDIM / 2, 1);
    (void)in_sizes; (void)n_in; (void)out_size;
}

// round 17
// speedup vs baseline: 1.1507x; 1.0332x over previous
#include <cuda_runtime.h>
#include <cuda_fp16.h>
#include <cstdint>

// Problem constants (fixed shapes)
#define T_TOK 4096
#define HDIM  1024
#define FDIM  4096
#define EDIM  8
#define BM 128
#define BN 128
#define BKH 64          // K halves per slab (4 x k16 mma steps)
#define ROWB 144        // smem row stride bytes (128 data + 16 pad)
#define PADROWS 9216    // 8192 + 8*128 worst-case segment padding
#define NS1 (HDIM / BKH)       // 16
#define NS2H (FDIM / 2 / BKH)  // 32 slabs per gemm2 K-half

// ---------------- scratch (static device globals; no allocation) ----------
__device__ __align__(16) __half g_wgup[(size_t)EDIM * 2 * FDIM * HDIM];
__device__ __align__(16) __half g_wdw[(size_t)EDIM * HDIM * FDIM];
__device__ __align__(16) __half g_x16[(size_t)T_TOK * HDIM];
__device__ __align__(16) __half g_h[(size_t)PADROWS * FDIM];
__device__ __align__(16) float  g_y[(size_t)PADROWS * HDIM];
__device__ int   g_perm_token[PADROWS];
__device__ float g_perm_weight[PADROWS];
__device__ int   g_te[T_TOK * 2];
__device__ float g_tw[T_TOK * 2];
__device__ int   g_counts[EDIM];
__device__ int   g_cursor[EDIM];
__device__ int   g_off[EDIM + 1];

// ---------------- helpers ---------------------------------------------------
__device__ __forceinline__ uint32_t h2u(__half2 h) { return *(uint32_t*)&h; }

__device__ __forceinline__ uint32_t smem_u32(const void* p) {
    uint32_t a;
    asm("{ .reg .u64 t; cvta.to.shared.u64 t, %1; cvt.u32.u64 %0, t; }"
        : "=r"(a) : "l"(p));
    return a;
}

__device__ __forceinline__ void ldsm4(uint32_t& r0, uint32_t& r1,
                                      uint32_t& r2, uint32_t& r3, uint32_t addr) {
    asm volatile("ldmatrix.sync.aligned.m8n8.x4.shared.b16 {%0,%1,%2,%3}, [%4];"
                 : "=r"(r0), "=r"(r1), "=r"(r2), "=r"(r3) : "r"(addr));
}

__device__ __forceinline__ void mma_f16(float c[4], const uint32_t a[4],
                                        uint32_t b0, uint32_t b1) {
    asm volatile(
        "mma.sync.aligned.m16n8k16.row.col.f32.f16.f16.f32 "
        "{%0,%1,%2,%3}, {%4,%5,%6,%7}, {%8,%9}, {%0,%1,%2,%3};\n"
        : "+f"(c[0]), "+f"(c[1]), "+f"(c[2]), "+f"(c[3])
        : "r"(a[0]), "r"(a[1]), "r"(a[2]), "r"(a[3]), "r"(b0), "r"(b1));
}

// ---------------- fp32 -> fp16 conversion (flat) -------------------------------
__global__ void cvt_kernel(const float* __restrict__ s, __half* __restrict__ d,
                           int n8) {
    int i = blockIdx.x * blockDim.x + threadIdx.x;
    if (i >= n8) return;
    const float4* s4 = (const float4*)s + (size_t)i * 2;
    float4 v0 = s4[0], v1 = s4[1];
    uint4 o;
    o.x = h2u(__floats2half2_rn(v0.x, v0.y));
    o.y = h2u(__floats2half2_rn(v0.z, v0.w));
    o.z = h2u(__floats2half2_rn(v1.x, v1.y));
    o.w = h2u(__floats2half2_rn(v1.z, v1.w));
    ((uint4*)d)[i] = o;
}

// ---------------- cvt for one column-half of gate_up ---------------------------
__global__ void cvt_gup_half_kernel(const float* __restrict__ s,
                                    __half* __restrict__ d, int half) {
    int i = blockIdx.x * blockDim.x + threadIdx.x;
    if (i >= EDIM * 4096 * 128) return;
    int rowIdx = i >> 7;
    int chunk = i & 127;
    int e = rowIdx >> 12;
    int rr = rowIdx & 4095;
    int isUp = rr >> 11;
    int r = rr & 2047;
    size_t srcRow = (size_t)e * 8192 + (size_t)isUp * 4096 +
                    (size_t)half * 2048 + (size_t)r;
    size_t off8 = srcRow * 128 + chunk;
    const float4* s4 = (const float4*)s + off8 * 2;
    float4 v0 = s4[0], v1 = s4[1];
    uint4 o;
    o.x = h2u(__floats2half2_rn(v0.x, v0.y));
    o.y = h2u(__floats2half2_rn(v0.z, v0.w));
    o.z = h2u(__floats2half2_rn(v1.x, v1.y));
    o.w = h2u(__floats2half2_rn(v1.z, v1.w));
    ((uint4*)d)[off8] = o;
}

// ---------------- init + zero output ------------------------------------------
__global__ void init_kernel() {
    int i = blockIdx.x * blockDim.x + threadIdx.x;
    if (i < PADROWS) {
        g_perm_token[i] = -1;
        g_perm_weight[i] = 0.f;
    }
    if (i < EDIM) g_counts[i] = 0;
}

__global__ void zero_out_kernel(float* __restrict__ out) {
    int i = blockIdx.x * blockDim.x + threadIdx.x;
    if (i < T_TOK * HDIM / 4)
        ((float4*)out)[i] = make_float4(0.f, 0.f, 0.f, 0.f);
}

// ---------------- router: logits + softmax top2 -----------------------------
__global__ void __launch_bounds__(128) router_kernel(
    const float* __restrict__ x, const float* __restrict__ gw,
    float* __restrict__ logits_out) {
    __shared__ float sgw[EDIM * HDIM];
    int tid = threadIdx.x;
    for (int i = tid; i < EDIM * HDIM; i += 128) sgw[i] = gw[i];
    __syncthreads();

    int warp = tid >> 5, lane = tid & 31;
    int t = blockIdx.x * 4 + warp;
    const float* xr = x + (size_t)t * HDIM;

    float acc[EDIM];
#pragma unroll
    for (int e = 0; e < EDIM; e++) acc[e] = 0.f;
    for (int j = lane; j < HDIM; j += 32) {
        float xv = xr[j];
#pragma unroll
        for (int e = 0; e < EDIM; e++) acc[e] = fmaf(xv, sgw[e * HDIM + j], acc[e]);
    }
#pragma unroll
    for (int e = 0; e < EDIM; e++)
#pragma unroll
        for (int o = 16; o > 0; o >>= 1)
            acc[e] += __shfl_xor_sync(0xffffffffu, acc[e], o);

    if (lane == 0) {
#pragma unroll
        for (int e = 0; e < EDIM; e++) logits_out[t * EDIM + e] = acc[e];
        int e0 = 0; float l0 = acc[0];
#pragma unroll
        for (int e = 1; e < EDIM; e++) if (acc[e] > l0) { l0 = acc[e]; e0 = e; }
        int e1 = -1; float l1 = -3.4e38f;
#pragma unroll
        for (int e = 0; e < EDIM; e++)
            if (e != e0 && acc[e] > l1) { l1 = acc[e]; e1 = e; }
        float r = expf(l1 - l0);
        float w0 = 1.f / (1.f + r);
        float w1 = r / (1.f + r);
        g_te[t * 2 + 0] = e0; g_tw[t * 2 + 0] = w0;
        g_te[t * 2 + 1] = e1; g_tw[t * 2 + 1] = w1;
        atomicAdd(&g_counts[e0], 1);
        atomicAdd(&g_counts[e1], 1);
    }
}

// ---------------- scan ------------------------------------------------------
__global__ void scan_kernel() {
    int off = 0;
    for (int e = 0; e < EDIM; e++) {
        g_off[e] = off;
        g_cursor[e] = off;
        off += ((g_counts[e] + BM - 1) / BM) * BM;
    }
    g_off[EDIM] = off;
}

// ---------------- scatter ---------------------------------------------------
__global__ void scatter_kernel() {
    int t = blockIdx.x * blockDim.x + threadIdx.x;
    if (t >= T_TOK) return;
#pragma unroll
    for (int k = 0; k < 2; k++) {
        int e = g_te[t * 2 + k];
        int pos = atomicAdd(&g_cursor[e], 1);
        g_perm_token[pos] = t;
        g_perm_weight[pos] = g_tw[t * 2 + k];
    }
}

// ---------------- GEMM1: h = silu(x@w1^T) * (x@w3^T) * route_w ---------------
__global__ void __launch_bounds__(256, 1) gemm1_kernel(int n0base) {
    extern __shared__ char sm1[];
    const uint32_t ABUF = 128 * ROWB;
    const uint32_t GOFF = 128 * ROWB;
    const uint32_t BBUF = 2 * 128 * ROWB;
    char* Asm = sm1;
    char* Bsm = sm1 + 2 * ABUF;
    uint32_t asB = smem_u32(Asm);
    uint32_t bsB = smem_u32(Bsm);

    int m0 = blockIdx.x * BM;
    if (m0 >= g_off[EDIM]) return;
    int n0 = n0base + blockIdx.y * BN;
    int e = 0;
    while (m0 >= g_off[e + 1]) e++;

    int tid = threadIdx.x;
    int r = tid >> 1;
    int seg = tid & 1;

    int tok = g_perm_token[m0 + r];
    const __half* arow = (tok >= 0)
        ? g_x16 + (size_t)tok * HDIM + seg * 32 : nullptr;
    const __half* bgrow = g_wgup + ((size_t)e * 2 * FDIM + (n0 + r)) * HDIM + seg * 32;
    const __half* burow = bgrow + (size_t)FDIM * HDIM;
    uint32_t stoff = (uint32_t)(r * ROWB + seg * 64);

    int warp = tid >> 5, lane = tid & 31;
    int gid = lane >> 2, tig = lane & 3;
    int wm = (warp & 1) * 64;
    int wn = (warp >> 1) * 32;

    uint32_t aLrow = (uint32_t)(wm + (lane & 15));
    uint32_t aLcol = (uint32_t)((lane >> 4) * 16);
    uint32_t bLrow = (uint32_t)(wn + (lane & 7) + ((lane >> 4) & 1) * 8);
    uint32_t bLcol = (uint32_t)(((lane >> 3) & 1) * 16);

    float acc[2][4][4][4];
#pragma unroll
    for (int g = 0; g < 2; g++)
#pragma unroll
        for (int mt = 0; mt < 4; mt++)
#pragma unroll
            for (int nt = 0; nt < 4; nt++)
#pragma unroll
                for (int i = 0; i < 4; i++) acc[g][mt][nt][i] = 0.f;

    const uint4 z4 = make_uint4(0, 0, 0, 0);
    uint4 pA[4], pG[4], pU[4];
#pragma unroll
    for (int i = 0; i < 4; i++) {
        pA[i] = arow ? *(const uint4*)(arow + i * 8) : z4;
        pG[i] = *(const uint4*)(bgrow + i * 8);
        pU[i] = *(const uint4*)(burow + i * 8);
    }

    for (int s = 0; s < NS1; s++) {
        int buf = s & 1;
        char* At = Asm + buf * ABUF;
        char* Bt = Bsm + buf * BBUF;
#pragma unroll
        for (int i = 0; i < 4; i++) {
            *(uint4*)(At + stoff + i * 16) = pA[i];
            *(uint4*)(Bt + stoff + i * 16) = pG[i];
            *(uint4*)(Bt + GOFF + stoff + i * 16) = pU[i];
        }
        __syncthreads();

        if (s + 1 < NS1) {
            int k = (s + 1) * BKH;
#pragma unroll
            for (int i = 0; i < 4; i++) {
                pA[i] = arow ? *(const uint4*)(arow + k + i * 8) : z4;
                pG[i] = *(const uint4*)(bgrow + k + i * 8);
                pU[i] = *(const uint4*)(burow + k + i * 8);
            }
        }

        uint32_t aTile = asB + buf * ABUF;
        uint32_t bTile = bsB + buf * BBUF;
#pragma unroll
        for (int ks = 0; ks < 4; ks++) {
            uint32_t kbA = ks * 32 + aLcol;
            uint32_t kbB = ks * 32 + bLcol;
            uint32_t a[4][4];
#pragma unroll
            for (int mt = 0; mt < 4; mt++)
                ldsm4(a[mt][0], a[mt][1], a[mt][2], a[mt][3],
                      aTile + (aLrow + mt * 16) * ROWB + kbA);
#pragma unroll
            for (int g = 0; g < 2; g++) {
#pragma unroll
                for (int np = 0; np < 2; np++) {
                    uint32_t b0, b1, b2, b3;
                    ldsm4(b0, b1, b2, b3,
                          bTile + g * GOFF + (bLrow + np * 16) * ROWB + kbB);
#pragma unroll
                    for (int mt = 0; mt < 4; mt++) {
                        mma_f16(acc[g][mt][np * 2 + 0], a[mt], b0, b1);
                        mma_f16(acc[g][mt][np * 2 + 1], a[mt], b2, b3);
                    }
                }
            }
        }
    }

#pragma unroll
    for (int mt = 0; mt < 4; mt++) {
        int rbase = m0 + wm + mt * 16 + gid;
        float wA = g_perm_weight[rbase];
        float wB = g_perm_weight[rbase + 8];
#pragma unroll
        for (int nt = 0; nt < 4; nt++) {
            int cbase = n0 + wn + nt * 8 + 2 * tig;
            float h0 = (acc[0][mt][nt][0] / (1.f + expf(-acc[0][mt][nt][0]))) *
                       acc[1][mt][nt][0] * wA;
            float h1 = (acc[0][mt][nt][1] / (1.f + expf(-acc[0][mt][nt][1]))) *
                       acc[1][mt][nt][1] * wA;
            float h2 = (acc[0][mt][nt][2] / (1.f + expf(-acc[0][mt][nt][2]))) *
                       acc[1][mt][nt][2] * wB;
            float h3 = (acc[0][mt][nt][3] / (1.f + expf(-acc[0][mt][nt][3]))) *
                       acc[1][mt][nt][3] * wB;
            *(uint32_t*)&g_h[(size_t)rbase * FDIM + cbase] =
                h2u(__floats2half2_rn(h0, h1));
            *(uint32_t*)&g_h[(size_t)(rbase + 8) * FDIM + cbase] =
                h2u(__floats2half2_rn(h2, h3));
        }
    }
}

// ---------------- GEMM2 (K-split): stageB=0 writes g_y partial over K half 0;
//                  stageB=1 computes K half 1, adds g_y, atomicAdds into out. ---
__global__ void __launch_bounds__(256, 1) gemm2_kernel(float* __restrict__ out,
                                                       int kbase, int stageB) {
    extern __shared__ char sm2[];
    const uint32_t ABUF = 128 * ROWB;
    const uint32_t BBUF = 128 * ROWB;
    char* Asm = sm2;
    char* Bsm = sm2 + 2 * ABUF;
    uint32_t asB = smem_u32(Asm);
    uint32_t bsB = smem_u32(Bsm);

    int m0 = blockIdx.x * BM;
    if (m0 >= g_off[EDIM]) return;
    int n0 = blockIdx.y * BN;
    int e = 0;
    while (m0 >= g_off[e + 1]) e++;

    int tid = threadIdx.x;
    int r = tid >> 1;
    int seg = tid & 1;

    const __half* arow = g_h + (size_t)(m0 + r) * FDIM + kbase + seg * 32;
    const __half* brow = g_wdw + ((size_t)e * HDIM + (n0 + r)) * FDIM + kbase + seg * 32;
    uint32_t stoff = (uint32_t)(r * ROWB + seg * 64);

    int warp = tid >> 5, lane = tid & 31;
    int gid = lane >> 2, tig = lane & 3;
    int wm = (warp & 1) * 64;
    int wn = (warp >> 1) * 32;

    uint32_t aLrow = (uint32_t)(wm + (lane & 15));
    uint32_t aLcol = (uint32_t)((lane >> 4) * 16);
    uint32_t bLrow = (uint32_t)(wn + (lane & 7) + ((lane >> 4) & 1) * 8);
    uint32_t bLcol = (uint32_t)(((lane >> 3) & 1) * 16);

    float acc[4][4][4];
#pragma unroll
    for (int mt = 0; mt < 4; mt++)
#pragma unroll
        for (int nt = 0; nt < 4; nt++)
#pragma unroll
            for (int i = 0; i < 4; i++) acc[mt][nt][i] = 0.f;

    uint4 pA[4], pB[4];
#pragma unroll
    for (int i = 0; i < 4; i++) {
        pA[i] = *(const uint4*)(arow + i * 8);
        pB[i] = *(const uint4*)(brow + i * 8);
    }

    for (int s = 0; s < NS2H; s++) {
        int buf = s & 1;
        char* At = Asm + buf * ABUF;
        char* Bt = Bsm + buf * BBUF;
#pragma unroll
        for (int i = 0; i < 4; i++) {
            *(uint4*)(At + stoff + i * 16) = pA[i];
            *(uint4*)(Bt + stoff + i * 16) = pB[i];
        }
        __syncthreads();

        if (s + 1 < NS2H) {
            int k = (s + 1) * BKH;
#pragma unroll
            for (int i = 0; i < 4; i++) {
                pA[i] = *(const uint4*)(arow + k + i * 8);
                pB[i] = *(const uint4*)(brow + k + i * 8);
            }
        }

        uint32_t aTile = asB + buf * ABUF;
        uint32_t bTile = bsB + buf * BBUF;
#pragma unroll
        for (int ks = 0; ks < 4; ks++) {
            uint32_t kbA = ks * 32 + aLcol;
            uint32_t kbB = ks * 32 + bLcol;
            uint32_t a[4][4];
#pragma unroll
            for (int mt = 0; mt < 4; mt++)
                ldsm4(a[mt][0], a[mt][1], a[mt][2], a[mt][3],
                      aTile + (aLrow + mt * 16) * ROWB + kbA);
#pragma unroll
            for (int np = 0; np < 2; np++) {
                uint32_t b0, b1, b2, b3;
                ldsm4(b0, b1, b2, b3,
                      bTile + (bLrow + np * 16) * ROWB + kbB);
#pragma unroll
                for (int mt = 0; mt < 4; mt++) {
                    mma_f16(acc[mt][np * 2 + 0], a[mt], b0, b1);
                    mma_f16(acc[mt][np * 2 + 1], a[mt], b2, b3);
                }
            }
        }
    }

    if (!stageB) {
        // stage A: write fp32 partials to g_y (row-unique -> deterministic)
#pragma unroll
        for (int mt = 0; mt < 4; mt++) {
            int rbase = m0 + wm + mt * 16 + gid;
#pragma unroll
            for (int nt = 0; nt < 4; nt++) {
                int cbase = n0 + wn + nt * 8 + 2 * tig;
                *(float2*)&g_y[(size_t)rbase * HDIM + cbase] =
                    make_float2(acc[mt][nt][0], acc[mt][nt][1]);
                *(float2*)&g_y[(size_t)(rbase + 8) * HDIM + cbase] =
                    make_float2(acc[mt][nt][2], acc[mt][nt][3]);
            }
        }
    } else {
        // stage B: total = partial + acc; atomicAdd into out (2 contributors
        // per element -> commutative -> deterministic)
#pragma unroll
        for (int mt = 0; mt < 4; mt++) {
            int rbase = m0 + wm + mt * 16 + gid;
            int tok0 = g_perm_token[rbase];
            int tok1 = g_perm_token[rbase + 8];
#pragma unroll
            for (int nt = 0; nt < 4; nt++) {
                int cbase = n0 + wn + nt * 8 + 2 * tig;
                float2 y0 = *(float2*)&g_y[(size_t)rbase * HDIM + cbase];
                float2 y1 = *(float2*)&g_y[(size_t)(rbase + 8) * HDIM + cbase];
                if (tok0 >= 0) {
                    atomicAdd(&out[(size_t)tok0 * HDIM + cbase],
                              acc[mt][nt][0] + y0.x);
                    atomicAdd(&out[(size_t)tok0 * HDIM + cbase + 1],
                              acc[mt][nt][1] + y0.y);
                }
                if (tok1 >= 0) {
                    atomicAdd(&out[(size_t)tok1 * HDIM + cbase],
                              acc[mt][nt][2] + y1.x);
                    atomicAdd(&out[(size_t)tok1 * HDIM + cbase + 1],
                              acc[mt][nt][3] + y1.y);
                }
            }
        }
    }
}

// ---------------- launcher ----------------------------------------------------
extern "C" void kernel_launch(void* const* d_in, const int* in_sizes, int n_in,
                              void* d_out, int out_size) {
    const float* x   = (const float*)d_in[0];   // (2,2048,1024)
    const float* gw  = (const float*)d_in[1];   // (8,1024)
    const float* gup = (const float*)d_in[2];   // (8,8192,1024)
    const float* dw  = (const float*)d_in[3];   // (8,1024,4096)
    float* out = (float*)d_out;                 // out (4194304) ++ logits (32768)
    float* logits = out + (size_t)T_TOK * HDIM;

    const int smem1 = 2 * 128 * ROWB + 2 * 2 * 128 * ROWB;  // 110592 B
    const int smem2 = 2 * 128 * ROWB + 2 * 128 * ROWB;      //  73728 B
    cudaFuncSetAttribute(gemm1_kernel, cudaFuncAttributeMaxDynamicSharedMemorySize, smem1);
    cudaFuncSetAttribute(gemm2_kernel, cudaFuncAttributeMaxDynamicSharedMemorySize, smem2);

    __half* d_wgup; cudaGetSymbolAddress((void**)&d_wgup, g_wgup);
    __half* d_wdw;  cudaGetSymbolAddress((void**)&d_wdw,  g_wdw);
    __half* d_x16;  cudaGetSymbolAddress((void**)&d_x16,  g_x16);

    static cudaStream_t s2 = nullptr, s3 = nullptr, s4 = nullptr;
    static cudaEvent_t evFork = nullptr, evCvt0 = nullptr, evH1 = nullptr,
                       evDW = nullptr, evRoute = nullptr, evG1h0 = nullptr,
                       evA = nullptr;
    if (!s2) {
        cudaStreamCreateWithFlags(&s2, cudaStreamNonBlocking);
        cudaStreamCreateWithFlags(&s3, cudaStreamNonBlocking);
        cudaStreamCreateWithFlags(&s4, cudaStreamNonBlocking);
        cudaEventCreateWithFlags(&evFork, cudaEventDisableTiming);
        cudaEventCreateWithFlags(&evCvt0, cudaEventDisableTiming);
        cudaEventCreateWithFlags(&evH1, cudaEventDisableTiming);
        cudaEventCreateWithFlags(&evDW, cudaEventDisableTiming);
        cudaEventCreateWithFlags(&evRoute, cudaEventDisableTiming);
        cudaEventCreateWithFlags(&evG1h0, cudaEventDisableTiming);
        cudaEventCreateWithFlags(&evA, cudaEventDisableTiming);
    }

    cudaEventRecord(evFork, 0);
    cudaStreamWaitEvent(s3, evFork, 0);

    // s3: output zero + routing chain (hidden under cvts on main)
    zero_out_kernel<<<(T_TOK * HDIM / 4 + 255) / 256, 256, 0, s3>>>(out);
    init_kernel<<<(PADROWS + 255) / 256, 256, 0, s3>>>();
    router_kernel<<<T_TOK / 4, 128, 0, s3>>>(x, gw, logits);
    scan_kernel<<<1, 1, 0, s3>>>();
    scatter_kernel<<<(T_TOK + 255) / 256, 256, 0, s3>>>();
    cudaEventRecord(evRoute, s3);

    // main: x cvt + first gate_up half (minimal serial prefix)
    cvt_kernel<<<(T_TOK * HDIM / 8 + 255) / 256, 256>>>(x, d_x16,
        T_TOK * HDIM / 8);
    cvt_gup_half_kernel<<<(EDIM * 4096 * 128 + 255) / 256, 256>>>(gup, d_wgup, 0);
    cudaEventRecord(evCvt0, 0);

    // s2: second gate_up half + down weights (overlap gemm1 half 0)
    cudaStreamWaitEvent(s2, evCvt0, 0);
    cvt_gup_half_kernel<<<(EDIM * 4096 * 128 + 255) / 256, 256, 0, s2>>>(
        gup, d_wgup, 1);
    cudaEventRecord(evH1, s2);
    cvt_kernel<<<(EDIM * HDIM * FDIM / 8 + 255) / 256, 256, 0, s2>>>(
        dw, d_wdw, EDIM * HDIM * FDIM / 8);
    cudaEventRecord(evDW, s2);

    // main: gemm1 half 0 (produces g_h cols [0,2048))
    cudaStreamWaitEvent(0, evRoute, 0);
    gemm1_kernel<<<dim3(PADROWS / BM, 16), 256, smem1>>>(0);
    cudaEventRecord(evG1h0, 0);

    // s4: gemm2 stage A (K half 0) — overlaps gemm1 half 1, fills its tail
    cudaStreamWaitEvent(s4, evG1h0, 0);
    cudaStreamWaitEvent(s4, evDW, 0);
    gemm2_kernel<<<dim3(PADROWS / BM, HDIM / BN), 256, smem2, s4>>>(out, 0, 0);
    cudaEventRecord(evA, s4);

    // main: gemm1 half 1, then gemm2 stage B (needs g_h cols [2048,4096) + g_y)
    cudaStreamWaitEvent(0, evH1, 0);
    gemm1_kernel<<<dim3(PADROWS / BM, 16), 256, smem1>>>(2048);
    cudaStreamWaitEvent(0, evA, 0);
    gemm2_kernel<<<dim3(PADROWS / BM, HDIM / BN), 256, smem2>>>(out, FDIM / 2, 1);
    (void)in_sizes; (void)n_in; (void)out_size;
}